// round 12
// baseline (speedup 1.0000x reference)
#include <cuda_runtime.h>
#include <cuda_bf16.h>
#include <mma.h>
#include <math.h>
#include <cstdint>

using namespace nvcuda;
typedef __nv_bfloat16 bf16;

#define LN_EPS 1e-5f

// persistent scratch (device globals: allocation-free)
__device__ float g_xres[(size_t)200704 * 192];        // mid residual
__device__ bf16  g_qkv [(size_t)200704 * 576];        // LN1 @ Wqkv^T + b
__device__ bf16  g_attno[(size_t)200704 * 192];       // attention output (pre-proj)
__device__ bf16  g_hmid[(size_t)200704 * 768];        // GELU(fc1)
__device__ bf16  g_wqkv[576 * 192];
__device__ bf16  g_wproj[192 * 192];
__device__ bf16  g_wfc1[768 * 192];
__device__ bf16  g_wfc2[192 * 768];

typedef wmma::fragment<wmma::matrix_a, 16, 16, 16, bf16, wmma::row_major> FA;
typedef wmma::fragment<wmma::matrix_b, 16, 16, 16, bf16, wmma::col_major> FBc;
typedef wmma::fragment<wmma::matrix_b, 16, 16, 16, bf16, wmma::row_major> FBr;
typedef wmma::fragment<wmma::accumulator, 16, 16, 16, float> FC;

// ---------------------------------------------------------------------------
__device__ __forceinline__ void cpa16(void* smem_dst, const void* gsrc) {
    unsigned int a = (unsigned int)__cvta_generic_to_shared(smem_dst);
    asm volatile("cp.async.cg.shared.global [%0], [%1], 16;\n" :: "r"(a), "l"(gsrc));
}
#define CP_COMMIT() asm volatile("cp.async.commit_group;\n" ::: "memory")
#define CP_WAIT0()  asm volatile("cp.async.wait_group 0;\n" ::: "memory")

// ---------------------------------------------------------------------------
__global__ void cvt_all(const float* __restrict__ wqkv, const float* __restrict__ wproj,
                        const float* __restrict__ wfc1, const float* __restrict__ wfc2)
{
    int i = blockIdx.x * 256 + threadIdx.x;
    if (i < 110592) g_wqkv[i]  = __float2bfloat16(wqkv[i]);
    if (i < 36864)  g_wproj[i] = __float2bfloat16(wproj[i]);
    if (i < 147456) {
        g_wfc1[i] = __float2bfloat16(wfc1[i]);
        g_wfc2[i] = __float2bfloat16(wfc2[i]);
    }
}

// ---------------------------------------------------------------------------
// smem (K=192 kernels): As 128x200 bf16 (51200) | Bbuf0/1 96x104 bf16 (19968
// each) | epi buf 64x52 f32 (13312)  = 104448 B -> 2 CTAs/SM
// ---------------------------------------------------------------------------
#define G192_SM (51200 + 2 * 19968 + 13312)
#define FC2_SM  (2 * 26624 + 2 * 19968 + 13312)

__device__ __forceinline__ void stage_A_ln(bf16* As, const float* __restrict__ xr,
                                           const float* __restrict__ g,
                                           const float* __restrict__ b,
                                           int wid, int lane)
{
    for (int r = wid; r < 128; r += 8) {
        float v[6]; float s = 0.f;
#pragma unroll
        for (int j = 0; j < 6; j++) { v[j] = xr[r * 192 + j * 32 + lane]; s += v[j]; }
#pragma unroll
        for (int o = 16; o; o >>= 1) s += __shfl_xor_sync(0xffffffffu, s, o);
        float mu = s * (1.f / 192.f);
        float va = 0.f;
#pragma unroll
        for (int j = 0; j < 6; j++) { float d = v[j] - mu; va += d * d; }
#pragma unroll
        for (int o = 16; o; o >>= 1) va += __shfl_xor_sync(0xffffffffu, va, o);
        float rstd = rsqrtf(va * (1.f / 192.f) + LN_EPS);
#pragma unroll
        for (int j = 0; j < 6; j++) {
            int c = j * 32 + lane;
            As[r * 200 + c] = __float2bfloat16((v[j] - mu) * rstd * g[c] + b[c]);
        }
    }
}

// async-copy one 96x96 B tile (rows of W[N,K] at n0.., cols k0..): 1152 x 16B
__device__ __forceinline__ void copy_B_tile(bf16* Bs, const bf16* __restrict__ W,
                                            int ldw, int n0, int k0, int tid)
{
    const bf16* src = W + (size_t)n0 * ldw + k0;
    for (int idx = tid; idx < 96 * 12; idx += 256) {
        int r = idx / 12, ch = (idx - r * 12) * 8;
        cpa16(Bs + r * 104 + ch, src + (size_t)r * ldw + ch);
    }
}

// async-copy 128x96 A chunk (ld 104)
__device__ __forceinline__ void copy_A_chunk(bf16* Ad, const bf16* __restrict__ src,
                                             int lds, int tid)
{
    for (int idx = tid; idx < 128 * 12; idx += 256) {
        int r = idx / 12, ch = (idx - r * 12) * 8;
        cpa16(Ad + r * 104 + ch, src + (size_t)r * lds + ch);
    }
}

// mma over one 96-K chunk: A from As (ld ldA, k offset kbase), B from Bs (ld 104)
__device__ __forceinline__ void mma_chunk(const bf16* As, int ldA, int kbase,
                                          const bf16* Bs, int mt, int ng, FC acc[6])
{
#pragma unroll
    for (int kk = 0; kk < 96; kk += 16) {
        FA a0, a1;
        wmma::load_matrix_sync(a0, As + (mt * 32) * ldA + kbase + kk, ldA);
        wmma::load_matrix_sync(a1, As + (mt * 32 + 16) * ldA + kbase + kk, ldA);
#pragma unroll
        for (int j = 0; j < 3; j++) {
            FBc b;
            wmma::load_matrix_sync(b, Bs + (ng * 48 + j * 16) * 104 + kk, 104);
            wmma::mma_sync(acc[j],     a0, b, acc[j]);
            wmma::mma_sync(acc[j + 3], a1, b, acc[j + 3]);
        }
    }
}

// ---------------------------------------------------------------------------
// Coalesced block-staged epilogue for one 128x96 slice (cols cbase..+95).
// 4 phases; phase ph covers rows [h*64, h*64+64) x cols [c*48, c*48+48),
// h=ph>>1, c=ph&1. Owning warps ((mt>>1)==h && ng==c) dump frags to buf
// (ld 52), then ALL 256 threads write coalesced (consecutive cols per lane).
// OP: 0=qkv(+b->bf16) 1=proj(+b+x->f32 g_xres) 2=fc1(+b,gelu->bf16)
// 3=fc2(+b+xres->out f32)
// ---------------------------------------------------------------------------
template <int OP>
__device__ __forceinline__ void epi_slice(float* buf, FC acc[6], int mt, int ng,
                                          int cbase, int row0,
                                          const float* __restrict__ xin,
                                          const float* __restrict__ bias,
                                          float* __restrict__ outp, int tid)
{
#pragma unroll
    for (int ph = 0; ph < 4; ph++) {
        const int h = ph >> 1, c = ph & 1;
        __syncthreads();
        if ((mt >> 1) == h && ng == c) {
            int lr = (mt & 1) * 32;
#pragma unroll
            for (int j = 0; j < 3; j++) {
                wmma::store_matrix_sync(buf + lr * 52 + j * 16,        acc[j],     52, wmma::mem_row_major);
                wmma::store_matrix_sync(buf + (lr + 16) * 52 + j * 16, acc[j + 3], 52, wmma::mem_row_major);
            }
        }
        __syncthreads();
        for (int idx = tid; idx < 64 * 48; idx += 256) {
            int r = idx / 48, cc = idx - r * 48;
            int gr = row0 + h * 64 + r;
            int gc = cbase + c * 48 + cc;
            float v = buf[r * 52 + cc] + bias[gc];
            if (OP == 0) {
                g_qkv[(size_t)gr * 576 + gc] = __float2bfloat16(v);
            } else if (OP == 1) {
                size_t gi = (size_t)gr * 192 + gc;
                g_xres[gi] = v + xin[gi];
            } else if (OP == 2) {
                v = 0.5f * v * (1.f + erff(v * 0.70710678118654752f));
                g_hmid[(size_t)gr * 768 + gc] = __float2bfloat16(v);
            } else {
                size_t gi = (size_t)gr * 192 + gc;
                outp[gi] = v + g_xres[gi];
            }
        }
    }
}

// ---------------------------------------------------------------------------
// Unified K=192 GEMM: CTA = 128 rows, N = NSLICES*96, cp.async-pipelined
// 96x96 B tiles, coalesced staged epilogue.
// OP: 0 = qkv (LN from xin), 1 = proj (A = g_attno, residual xin),
// 2 = fc1 (LN from g_xres).
// ---------------------------------------------------------------------------
template <int NSLICES, int OP>
__global__ __launch_bounds__(256) void gemm192_kernel(
    const float* __restrict__ xin, const float* __restrict__ lng,
    const float* __restrict__ lnb, const float* __restrict__ bias)
{
    extern __shared__ char smc[];
    bf16*  As   = (bf16*)smc;
    bf16*  Bb0  = (bf16*)(smc + 51200);
    bf16*  Bb1  = (bf16*)(smc + 51200 + 19968);
    float* buf  = (float*)(smc + 51200 + 2 * 19968);

    const bf16* W = (OP == 0) ? g_wqkv : ((OP == 1) ? g_wproj : g_wfc1);

    const int tid = threadIdx.x, wid = tid >> 5, lane = tid & 31;
    const int row0 = blockIdx.x * 128;
    const int mt = wid & 3, ng = wid >> 2;

    // prefetch tile 0 (and A for OP1) in one async group
    copy_B_tile(Bb0, W, 192, 0, 0, tid);
    if (OP == 1) {
        const bf16* src = g_attno + (size_t)row0 * 192;
        for (int idx = tid; idx < 128 * 24; idx += 256) {
            int r = idx / 24, ch = (idx - r * 24) * 8;
            cpa16(As + r * 200 + ch, src + (size_t)r * 192 + ch);
        }
    }
    CP_COMMIT();

    if (OP == 0) stage_A_ln(As, xin + (size_t)row0 * 192, lng, lnb, wid, lane);
    if (OP == 2) stage_A_ln(As, g_xres + (size_t)row0 * 192, lng, lnb, wid, lane);

    FC acc[6];
#pragma unroll
    for (int j = 0; j < 6; j++) wmma::fill_fragment(acc[j], 0.f);

    const int T = NSLICES * 2;
    for (int t = 0; t < T; t++) {
        const int s = t >> 1, c = t & 1;
        bf16* Bcur = (t & 1) ? Bb1 : Bb0;
        bf16* Bnxt = (t & 1) ? Bb0 : Bb1;
        CP_WAIT0();
        __syncthreads();            // Bcur ready; everyone done reading Bnxt
        if (t + 1 < T) {
            copy_B_tile(Bnxt, W, 192, ((t + 1) >> 1) * 96, ((t + 1) & 1) * 96, tid);
            CP_COMMIT();
        }
        mma_chunk(As, 200, c * 96, Bcur, mt, ng, acc);
        if (c == 1) {
            // next-slice B prefetch is already in flight; epilogue overlaps it
            epi_slice<OP>(buf, acc, mt, ng, s * 96, row0, xin, bias, (float*)0, tid);
#pragma unroll
            for (int j = 0; j < 6; j++) wmma::fill_fragment(acc[j], 0.f);
        }
    }
}

// ---------------------------------------------------------------------------
// FC2: grid (1568, 2); CTA = 128 rows x 96 cols, K = 768 in 8 cp.async-
// pipelined chunks, persistent acc; + residual -> out
// ---------------------------------------------------------------------------
__global__ __launch_bounds__(256) void fc2_kernel(
    const float* __restrict__ bfc2, float* __restrict__ out)
{
    extern __shared__ char smc[];
    bf16*  Ab0  = (bf16*)smc;
    bf16*  Ab1  = (bf16*)(smc + 26624);
    bf16*  Bb0  = (bf16*)(smc + 2 * 26624);
    bf16*  Bb1  = (bf16*)(smc + 2 * 26624 + 19968);
    float* buf  = (float*)(smc + 2 * 26624 + 2 * 19968);

    const int tid = threadIdx.x, wid = tid >> 5;
    const int row0 = blockIdx.x * 128;
    const int n0 = blockIdx.y * 96;
    const int mt = wid & 3, ng = wid >> 2;

    copy_A_chunk(Ab0, g_hmid + (size_t)row0 * 768, 768, tid);
    copy_B_tile(Bb0, g_wfc2, 768, n0, 0, tid);
    CP_COMMIT();

    FC acc[6];
#pragma unroll
    for (int j = 0; j < 6; j++) wmma::fill_fragment(acc[j], 0.f);

    for (int t = 0; t < 8; t++) {
        bf16* Acur = (t & 1) ? Ab1 : Ab0;
        bf16* Bcur = (t & 1) ? Bb1 : Bb0;
        bf16* Anxt = (t & 1) ? Ab0 : Ab1;
        bf16* Bnxt = (t & 1) ? Bb0 : Bb1;
        CP_WAIT0();
        __syncthreads();
        if (t + 1 < 8) {
            copy_A_chunk(Anxt, g_hmid + (size_t)row0 * 768 + (t + 1) * 96, 768, tid);
            copy_B_tile(Bnxt, g_wfc2, 768, n0, (t + 1) * 96, tid);
            CP_COMMIT();
        }
        mma_chunk(Acur, 104, 0, Bcur, mt, ng, acc);
    }
    epi_slice<3>(buf, acc, mt, ng, n0, row0, (const float*)0, bfc2, out, tid);
}

// ---------------------------------------------------------------------------
// attention core per (window, head): S -> masked softmax -> PV
// ---------------------------------------------------------------------------
#define AT_SM 41984

__global__ __launch_bounds__(256) void attn_core(const int* __restrict__ mask)
{
    extern __shared__ char smc[];
    bf16*  qs    = (bf16*)smc;               // 64x40
    bf16*  ks    = (bf16*)(smc + 5120);
    bf16*  vs    = (bf16*)(smc + 10240);
    float* S     = (float*)(smc + 15360);    // 64x68 f32
    bf16*  P     = (bf16*)(smc + 32768);     // 64x72
    float* pvbuf = (float*)(smc + 15360);    // alias S

    const int tid = threadIdx.x, wid = tid >> 5, lane = tid & 31;
    const int win = blockIdx.x, h = blockIdx.y;
    const size_t base = (size_t)(win * 49) * 576;

    {
        const int r = tid >> 2, c8 = (tid & 3) * 8;
        uint4 z; z.x = z.y = z.z = z.w = 0u;
#pragma unroll
        for (int m = 0; m < 3; m++) {
            bf16* dst = (m == 0) ? qs : ((m == 1) ? ks : vs);
            uint4 val = z;
            if (r < 49)
                val = *(const uint4*)(g_qkv + base + (size_t)r * 576 + m * 192 + h * 32 + c8);
            *(uint4*)(dst + r * 40 + c8) = val;
        }
    }
    __syncthreads();

#pragma unroll
    for (int it = 0; it < 2; it++) {
        int t = wid + it * 8;
        int mt = t & 3, nt = t >> 2;
        FC c;
        wmma::fill_fragment(c, 0.f);
#pragma unroll
        for (int k0 = 0; k0 < 32; k0 += 16) {
            FA a;
            wmma::load_matrix_sync(a, qs + mt * 16 * 40 + k0, 40);
            FBc b;
            wmma::load_matrix_sync(b, ks + nt * 16 * 40 + k0, 40);
            wmma::mma_sync(c, a, b, c);
        }
        wmma::store_matrix_sync(S + mt * 16 * 68 + nt * 16, c, 68, wmma::mem_row_major);
    }
    __syncthreads();

    {
        const float scale = 0.17677669529663687f;
        const int* mrow_base = mask + (size_t)win * 49 * 49;
        for (int r = wid; r < 49; r += 8) {
            const int* mrow = mrow_base + r * 49;
            int j2 = lane + 32;
            float s1 = (mrow[lane] == 0) ? -1e30f : S[r * 68 + lane] * scale;
            float s2 = (j2 < 49 && mrow[j2] != 0) ? S[r * 68 + j2] * scale : -1e30f;
            float m = fmaxf(s1, s2);
#pragma unroll
            for (int o = 16; o; o >>= 1) m = fmaxf(m, __shfl_xor_sync(0xffffffffu, m, o));
            float e1 = __expf(s1 - m);
            float e2 = (j2 < 49) ? __expf(s2 - m) : 0.f;
            float sum = e1 + e2;
#pragma unroll
            for (int o = 16; o; o >>= 1) sum += __shfl_xor_sync(0xffffffffu, sum, o);
            float inv = 1.f / sum;
            P[r * 72 + lane] = __float2bfloat16(e1 * inv);
            P[r * 72 + j2]   = __float2bfloat16(e2 * inv);
        }
    }
    __syncthreads();

    {
        int mt = wid & 3, nt = wid >> 2;
        FC c;
        wmma::fill_fragment(c, 0.f);
#pragma unroll
        for (int k0 = 0; k0 < 64; k0 += 16) {
            FA a;
            wmma::load_matrix_sync(a, P + mt * 16 * 72 + k0, 72);
            FBr b;
            wmma::load_matrix_sync(b, vs + k0 * 40 + nt * 16, 40);
            wmma::mma_sync(c, a, b, c);
        }
        wmma::store_matrix_sync(pvbuf + mt * 16 * 40 + nt * 16, c, 40, wmma::mem_row_major);
    }
    __syncthreads();

    for (int idx = tid; idx < 49 * 32; idx += 256) {
        int r = idx >> 5, c = idx & 31;
        g_attno[(size_t)(win * 49 + r) * 192 + h * 32 + c] = __float2bfloat16(pvbuf[r * 40 + c]);
    }
}

// ---------------------------------------------------------------------------

extern "C" void kernel_launch(void* const* d_in, const int* in_sizes, int n_in,
                              void* d_out, int out_size)
{
    const float* x     = (const float*)d_in[0];
    const int*   msk   = (const int*)  d_in[1];
    const float* ln1g  = (const float*)d_in[2];
    const float* ln1b  = (const float*)d_in[3];
    const float* bqkv  = (const float*)d_in[5];
    const float* bproj = (const float*)d_in[7];
    const float* ln2g  = (const float*)d_in[8];
    const float* ln2b  = (const float*)d_in[9];
    const float* bfc1  = (const float*)d_in[11];
    const float* bfc2  = (const float*)d_in[13];
    float* out = (float*)d_out;

    cudaFuncSetAttribute(gemm192_kernel<6, 0>, cudaFuncAttributeMaxDynamicSharedMemorySize, G192_SM);
    cudaFuncSetAttribute(gemm192_kernel<2, 1>, cudaFuncAttributeMaxDynamicSharedMemorySize, G192_SM);
    cudaFuncSetAttribute(gemm192_kernel<8, 2>, cudaFuncAttributeMaxDynamicSharedMemorySize, G192_SM);
    cudaFuncSetAttribute(fc2_kernel, cudaFuncAttributeMaxDynamicSharedMemorySize, FC2_SM);
    cudaFuncSetAttribute(attn_core,  cudaFuncAttributeMaxDynamicSharedMemorySize, AT_SM);

    cvt_all<<<576, 256>>>((const float*)d_in[4], (const float*)d_in[6],
                          (const float*)d_in[10], (const float*)d_in[12]);
    gemm192_kernel<6, 0><<<1568, 256, G192_SM>>>(x, ln1g, ln1b, bqkv);
    attn_core<<<dim3(4096, 6), 256, AT_SM>>>(msk);
    gemm192_kernel<2, 1><<<1568, 256, G192_SM>>>(x, (const float*)0, (const float*)0, bproj);
    gemm192_kernel<8, 2><<<1568, 256, G192_SM>>>((const float*)0, ln2g, ln2b, bfc1);
    fc2_kernel<<<dim3(1568, 2), 256, FC2_SM>>>(bfc2, out);
}

// round 13
// speedup vs baseline: 1.0457x; 1.0457x over previous
#include <cuda_runtime.h>
#include <cuda_bf16.h>
#include <mma.h>
#include <math.h>
#include <cstdint>

using namespace nvcuda;
typedef __nv_bfloat16 bf16;

#define LN_EPS 1e-5f

// persistent scratch (device globals: allocation-free)
__device__ float g_xres[(size_t)200704 * 192];        // mid residual
__device__ bf16  g_qkv [(size_t)200704 * 576];        // LN1 @ Wqkv^T + b
__device__ bf16  g_attno[(size_t)200704 * 192];       // attention output (pre-proj)
__device__ bf16  g_hmid[(size_t)200704 * 768];        // GELU(fc1)
__device__ bf16  g_wqkv[576 * 192];
__device__ bf16  g_wproj[192 * 192];
__device__ bf16  g_wfc1[768 * 192];
__device__ bf16  g_wfc2[192 * 768];

typedef wmma::fragment<wmma::matrix_a, 16, 16, 16, bf16, wmma::row_major> FA;
typedef wmma::fragment<wmma::matrix_b, 16, 16, 16, bf16, wmma::col_major> FBc;
typedef wmma::fragment<wmma::matrix_b, 16, 16, 16, bf16, wmma::row_major> FBr;
typedef wmma::fragment<wmma::accumulator, 16, 16, 16, float> FC;

// ---------------------------------------------------------------------------
__device__ __forceinline__ void cpa16(void* smem_dst, const void* gsrc) {
    unsigned int a = (unsigned int)__cvta_generic_to_shared(smem_dst);
    asm volatile("cp.async.cg.shared.global [%0], [%1], 16;\n" :: "r"(a), "l"(gsrc));
}
#define CP_COMMIT() asm volatile("cp.async.commit_group;\n" ::: "memory")
#define CP_WAIT0()  asm volatile("cp.async.wait_group 0;\n" ::: "memory")

// ---------------------------------------------------------------------------
__global__ void cvt_all(const float* __restrict__ wqkv, const float* __restrict__ wproj,
                        const float* __restrict__ wfc1, const float* __restrict__ wfc2)
{
    int i = blockIdx.x * 256 + threadIdx.x;
    if (i < 110592) g_wqkv[i]  = __float2bfloat16(wqkv[i]);
    if (i < 36864)  g_wproj[i] = __float2bfloat16(wproj[i]);
    if (i < 147456) {
        g_wfc1[i] = __float2bfloat16(wfc1[i]);
        g_wfc2[i] = __float2bfloat16(wfc2[i]);
    }
}

// ---------------------------------------------------------------------------
// smem (K=192 kernels): As 128x200 bf16 (51200) | Bbuf0/1 96x104 bf16 (19968
// each) | epi buf 64x52 f32 (13312)  = 104448 B -> 2 CTAs/SM
// ---------------------------------------------------------------------------
#define G192_SM (51200 + 2 * 19968 + 13312)
#define FC2_SM  (2 * 26624 + 2 * 19968 + 13312)

__device__ __forceinline__ void stage_A_ln(bf16* As, const float* __restrict__ xr,
                                           const float* __restrict__ g,
                                           const float* __restrict__ b,
                                           int wid, int lane)
{
    for (int r = wid; r < 128; r += 8) {
        float v[6]; float s = 0.f;
#pragma unroll
        for (int j = 0; j < 6; j++) { v[j] = xr[r * 192 + j * 32 + lane]; s += v[j]; }
#pragma unroll
        for (int o = 16; o; o >>= 1) s += __shfl_xor_sync(0xffffffffu, s, o);
        float mu = s * (1.f / 192.f);
        float va = 0.f;
#pragma unroll
        for (int j = 0; j < 6; j++) { float d = v[j] - mu; va += d * d; }
#pragma unroll
        for (int o = 16; o; o >>= 1) va += __shfl_xor_sync(0xffffffffu, va, o);
        float rstd = rsqrtf(va * (1.f / 192.f) + LN_EPS);
#pragma unroll
        for (int j = 0; j < 6; j++) {
            int c = j * 32 + lane;
            As[r * 200 + c] = __float2bfloat16((v[j] - mu) * rstd * g[c] + b[c]);
        }
    }
}

// async-copy one 96x96 B tile (rows of W[N,K] at n0.., cols k0..): 1152 x 16B
__device__ __forceinline__ void copy_B_tile(bf16* Bs, const bf16* __restrict__ W,
                                            int ldw, int n0, int k0, int tid)
{
    const bf16* src = W + (size_t)n0 * ldw + k0;
    for (int idx = tid; idx < 96 * 12; idx += 256) {
        int r = idx / 12, ch = (idx - r * 12) * 8;
        cpa16(Bs + r * 104 + ch, src + (size_t)r * ldw + ch);
    }
}

// async-copy 128x96 A chunk (ld 104)
__device__ __forceinline__ void copy_A_chunk(bf16* Ad, const bf16* __restrict__ src,
                                             int lds, int tid)
{
    for (int idx = tid; idx < 128 * 12; idx += 256) {
        int r = idx / 12, ch = (idx - r * 12) * 8;
        cpa16(Ad + r * 104 + ch, src + (size_t)r * lds + ch);
    }
}

// mma over one 96-K chunk: A from As (ld ldA, k offset kbase), B from Bs (ld 104)
__device__ __forceinline__ void mma_chunk(const bf16* As, int ldA, int kbase,
                                          const bf16* Bs, int mt, int ng, FC acc[6])
{
#pragma unroll
    for (int kk = 0; kk < 96; kk += 16) {
        FA a0, a1;
        wmma::load_matrix_sync(a0, As + (mt * 32) * ldA + kbase + kk, ldA);
        wmma::load_matrix_sync(a1, As + (mt * 32 + 16) * ldA + kbase + kk, ldA);
#pragma unroll
        for (int j = 0; j < 3; j++) {
            FBc b;
            wmma::load_matrix_sync(b, Bs + (ng * 48 + j * 16) * 104 + kk, 104);
            wmma::mma_sync(acc[j],     a0, b, acc[j]);
            wmma::mma_sync(acc[j + 3], a1, b, acc[j + 3]);
        }
    }
}

// ---------------------------------------------------------------------------
// Coalesced block-staged epilogue for one 128x96 slice (cols cbase..+95).
// 4 phases; phase ph covers rows [h*64, +64) x cols [c*48, +48).
// OP: 0=qkv(+b->bf16) 1=proj(+b+x->f32 g_xres) 2=fc1(+b,gelu->bf16)
// 3=fc2(+b+xres->out f32)
// ---------------------------------------------------------------------------
template <int OP>
__device__ __forceinline__ void epi_slice(float* buf, FC acc[6], int mt, int ng,
                                          int cbase, int row0,
                                          const float* __restrict__ xin,
                                          const float* __restrict__ bias,
                                          float* __restrict__ outp, int tid)
{
#pragma unroll
    for (int ph = 0; ph < 4; ph++) {
        const int h = ph >> 1, c = ph & 1;
        __syncthreads();
        if ((mt >> 1) == h && ng == c) {
            int lr = (mt & 1) * 32;
#pragma unroll
            for (int j = 0; j < 3; j++) {
                wmma::store_matrix_sync(buf + lr * 52 + j * 16,        acc[j],     52, wmma::mem_row_major);
                wmma::store_matrix_sync(buf + (lr + 16) * 52 + j * 16, acc[j + 3], 52, wmma::mem_row_major);
            }
        }
        __syncthreads();
        for (int idx = tid; idx < 64 * 48; idx += 256) {
            int r = idx / 48, cc = idx - r * 48;
            int gr = row0 + h * 64 + r;
            int gc = cbase + c * 48 + cc;
            float v = buf[r * 52 + cc] + bias[gc];
            if (OP == 0) {
                g_qkv[(size_t)gr * 576 + gc] = __float2bfloat16(v);
            } else if (OP == 1) {
                size_t gi = (size_t)gr * 192 + gc;
                g_xres[gi] = v + xin[gi];
            } else if (OP == 2) {
                v = 0.5f * v * (1.f + erff(v * 0.70710678118654752f));
                g_hmid[(size_t)gr * 768 + gc] = __float2bfloat16(v);
            } else {
                size_t gi = (size_t)gr * 192 + gc;
                outp[gi] = v + g_xres[gi];
            }
        }
    }
}

// ---------------------------------------------------------------------------
// Unified K=192 GEMM: CTA = 128 rows, N = NSLICES*96, cp.async-pipelined
// 96x96 B tiles, coalesced staged epilogue.
// ---------------------------------------------------------------------------
template <int NSLICES, int OP>
__global__ __launch_bounds__(256) void gemm192_kernel(
    const float* __restrict__ xin, const float* __restrict__ lng,
    const float* __restrict__ lnb, const float* __restrict__ bias)
{
    extern __shared__ char smc[];
    bf16*  As   = (bf16*)smc;
    bf16*  Bb0  = (bf16*)(smc + 51200);
    bf16*  Bb1  = (bf16*)(smc + 51200 + 19968);
    float* buf  = (float*)(smc + 51200 + 2 * 19968);

    const bf16* W = (OP == 0) ? g_wqkv : ((OP == 1) ? g_wproj : g_wfc1);

    const int tid = threadIdx.x, wid = tid >> 5, lane = tid & 31;
    const int row0 = blockIdx.x * 128;
    const int mt = wid & 3, ng = wid >> 2;

    copy_B_tile(Bb0, W, 192, 0, 0, tid);
    if (OP == 1) {
        const bf16* src = g_attno + (size_t)row0 * 192;
        for (int idx = tid; idx < 128 * 24; idx += 256) {
            int r = idx / 24, ch = (idx - r * 24) * 8;
            cpa16(As + r * 200 + ch, src + (size_t)r * 192 + ch);
        }
    }
    CP_COMMIT();

    if (OP == 0) stage_A_ln(As, xin + (size_t)row0 * 192, lng, lnb, wid, lane);
    if (OP == 2) stage_A_ln(As, g_xres + (size_t)row0 * 192, lng, lnb, wid, lane);

    FC acc[6];
#pragma unroll
    for (int j = 0; j < 6; j++) wmma::fill_fragment(acc[j], 0.f);

    const int T = NSLICES * 2;
    for (int t = 0; t < T; t++) {
        const int s = t >> 1, c = t & 1;
        bf16* Bcur = (t & 1) ? Bb1 : Bb0;
        bf16* Bnxt = (t & 1) ? Bb0 : Bb1;
        CP_WAIT0();
        __syncthreads();
        if (t + 1 < T) {
            copy_B_tile(Bnxt, W, 192, ((t + 1) >> 1) * 96, ((t + 1) & 1) * 96, tid);
            CP_COMMIT();
        }
        mma_chunk(As, 200, c * 96, Bcur, mt, ng, acc);
        if (c == 1) {
            epi_slice<OP>(buf, acc, mt, ng, s * 96, row0, xin, bias, (float*)0, tid);
#pragma unroll
            for (int j = 0; j < 6; j++) wmma::fill_fragment(acc[j], 0.f);
        }
    }
}

// ---------------------------------------------------------------------------
// FC2: grid 3136, paired: n0=(bid&1)*96, row0=(bid>>1)*128 so both 96-col
// slices of the same 128 rows run adjacently and share g_hmid reads in L2.
// K = 768 in 8 cp.async-pipelined chunks, persistent acc; + residual -> out
// ---------------------------------------------------------------------------
__global__ __launch_bounds__(256) void fc2_kernel(
    const float* __restrict__ bfc2, float* __restrict__ out)
{
    extern __shared__ char smc[];
    bf16*  Ab0  = (bf16*)smc;
    bf16*  Ab1  = (bf16*)(smc + 26624);
    bf16*  Bb0  = (bf16*)(smc + 2 * 26624);
    bf16*  Bb1  = (bf16*)(smc + 2 * 26624 + 19968);
    float* buf  = (float*)(smc + 2 * 26624 + 2 * 19968);

    const int tid = threadIdx.x, wid = tid >> 5;
    const int bid = blockIdx.x;
    const int row0 = (bid >> 1) * 128;
    const int n0 = (bid & 1) * 96;
    const int mt = wid & 3, ng = wid >> 2;

    copy_A_chunk(Ab0, g_hmid + (size_t)row0 * 768, 768, tid);
    copy_B_tile(Bb0, g_wfc2, 768, n0, 0, tid);
    CP_COMMIT();

    FC acc[6];
#pragma unroll
    for (int j = 0; j < 6; j++) wmma::fill_fragment(acc[j], 0.f);

    for (int t = 0; t < 8; t++) {
        bf16* Acur = (t & 1) ? Ab1 : Ab0;
        bf16* Bcur = (t & 1) ? Bb1 : Bb0;
        bf16* Anxt = (t & 1) ? Ab0 : Ab1;
        bf16* Bnxt = (t & 1) ? Bb0 : Bb1;
        CP_WAIT0();
        __syncthreads();
        if (t + 1 < 8) {
            copy_A_chunk(Anxt, g_hmid + (size_t)row0 * 768 + (t + 1) * 96, 768, tid);
            copy_B_tile(Bnxt, g_wfc2, 768, n0, (t + 1) * 96, tid);
            CP_COMMIT();
        }
        mma_chunk(Acur, 104, 0, Bcur, mt, ng, acc);
    }
    epi_slice<3>(buf, acc, mt, ng, n0, row0, (const float*)0, bfc2, out, tid);
}

// ---------------------------------------------------------------------------
// attention core v2: ONE CTA PER WINDOW, loop over 6 heads with cp.async
// double-buffered q/k/v head slices; mask converted once to 64-bit bitmasks.
// smem: qkv dbl 2x15360 | S 64x68 f32 17408 | P 64x72 bf16 9216 | mb 512
// = 57856 B -> 3 CTAs/SM
// ---------------------------------------------------------------------------
#define AT_SM (2 * 15360 + 17408 + 9216 + 512)

__device__ __forceinline__ void stage_qkv_head(bf16* dst, size_t base, int h, int tid)
{
    // 49 rows x 3 mats x 32 cols: 588 x 16B
    for (int idx = tid; idx < 588; idx += 256) {
        int m = idx / 196, rem = idx - m * 196;
        int r = rem >> 2, c8 = (rem & 3) * 8;
        cpa16(dst + m * 2560 + r * 40 + c8,
              g_qkv + base + (size_t)r * 576 + m * 192 + h * 32 + c8);
    }
}

__global__ __launch_bounds__(256) void attn_core(const int* __restrict__ mask)
{
    extern __shared__ char smc[];
    bf16*  qkvb0 = (bf16*)smc;                    // q@0 k@2560 v@5120 (elems)
    bf16*  qkvb1 = (bf16*)(smc + 15360);
    float* S     = (float*)(smc + 30720);         // 64x68 f32
    bf16*  P     = (bf16*)(smc + 48128);          // 64x72
    unsigned long long* mb = (unsigned long long*)(smc + 57344);
    float* pvbuf = S;                             // alias

    const int tid = threadIdx.x, wid = tid >> 5, lane = tid & 31;
    const int win = blockIdx.x;
    const size_t base = (size_t)(win * 49) * 576;

    // mask -> bitmask rows (once per window)
    {
        const int* mrow_base = mask + (size_t)win * 49 * 49;
        for (int r = wid; r < 49; r += 8) {
            const int* mrow = mrow_base + r * 49;
            unsigned m1 = __ballot_sync(0xffffffffu, mrow[lane] != 0);
            unsigned m2 = __ballot_sync(0xffffffffu,
                                        (lane + 32 < 49) ? (mrow[lane + 32] != 0) : 0);
            if (lane == 0) mb[r] = ((unsigned long long)m2 << 32) | m1;
        }
    }
    // zero v rows 49..63 in both buffers (padded rows must not be NaN)
    for (int idx = tid; idx < 150; idx += 256) {
        int b = idx / 75, e = idx - b * 75;
        int r = 49 + e / 5, c8 = (e % 5) * 8;
        bf16* vdst = (b ? qkvb1 : qkvb0) + 5120 + r * 40 + c8;
        uint4 z; z.x = z.y = z.z = z.w = 0u;
        *(uint4*)vdst = z;
    }

    stage_qkv_head(qkvb0, base, 0, tid);
    CP_COMMIT();
    __syncthreads();

    for (int h = 0; h < 6; h++) {
        bf16* cur = (h & 1) ? qkvb1 : qkvb0;
        bf16* nxt = (h & 1) ? qkvb0 : qkvb1;
        CP_WAIT0();
        __syncthreads();
        if (h + 1 < 6) {
            stage_qkv_head(nxt, base, h + 1, tid);
            CP_COMMIT();
        }
        bf16* qs = cur, *ks = cur + 2560, *vs = cur + 5120;

        // S = q k^T : 16 tiles, 2/warp
#pragma unroll
        for (int it = 0; it < 2; it++) {
            int t = wid + it * 8;
            int mt = t & 3, nt = t >> 2;
            FC c;
            wmma::fill_fragment(c, 0.f);
#pragma unroll
            for (int k0 = 0; k0 < 32; k0 += 16) {
                FA a;
                wmma::load_matrix_sync(a, qs + mt * 16 * 40 + k0, 40);
                FBc b;
                wmma::load_matrix_sync(b, ks + nt * 16 * 40 + k0, 40);
                wmma::mma_sync(c, a, b, c);
            }
            wmma::store_matrix_sync(S + mt * 16 * 68 + nt * 16, c, 68, wmma::mem_row_major);
        }
        __syncthreads();

        // masked softmax (bitmask) -> P bf16
        {
            const float scale = 0.17677669529663687f;
            for (int r = wid; r < 49; r += 8) {
                unsigned long long bits = mb[r];
                int j2 = lane + 32;
                bool m1 = (bits >> lane) & 1ull;
                bool m2 = (j2 < 49) && ((bits >> j2) & 1ull);
                float s1 = m1 ? S[r * 68 + lane] * scale : -1e30f;
                float s2 = m2 ? S[r * 68 + j2] * scale : -1e30f;
                float m = fmaxf(s1, s2);
#pragma unroll
                for (int o = 16; o; o >>= 1) m = fmaxf(m, __shfl_xor_sync(0xffffffffu, m, o));
                float e1 = __expf(s1 - m);
                float e2 = (j2 < 49) ? __expf(s2 - m) : 0.f;
                float sum = e1 + e2;
#pragma unroll
                for (int o = 16; o; o >>= 1) sum += __shfl_xor_sync(0xffffffffu, sum, o);
                float inv = 1.f / sum;
                P[r * 72 + lane] = __float2bfloat16(e1 * inv);
                P[r * 72 + j2]   = __float2bfloat16(e2 * inv);
            }
        }
        __syncthreads();

        // PV : 8 tiles, 1/warp
        {
            int mt = wid & 3, nt = wid >> 2;
            FC c;
            wmma::fill_fragment(c, 0.f);
#pragma unroll
            for (int k0 = 0; k0 < 64; k0 += 16) {
                FA a;
                wmma::load_matrix_sync(a, P + mt * 16 * 72 + k0, 72);
                FBr b;
                wmma::load_matrix_sync(b, vs + k0 * 40 + nt * 16, 40);
                wmma::mma_sync(c, a, b, c);
            }
            wmma::store_matrix_sync(pvbuf + mt * 16 * 40 + nt * 16, c, 40, wmma::mem_row_major);
        }
        __syncthreads();

        for (int idx = tid; idx < 49 * 32; idx += 256) {
            int r = idx >> 5, c = idx & 31;
            g_attno[(size_t)(win * 49 + r) * 192 + h * 32 + c] =
                __float2bfloat16(pvbuf[r * 40 + c]);
        }
        __syncthreads();   // pvbuf (=S) reused next head
    }
}

// ---------------------------------------------------------------------------

extern "C" void kernel_launch(void* const* d_in, const int* in_sizes, int n_in,
                              void* d_out, int out_size)
{
    const float* x     = (const float*)d_in[0];
    const int*   msk   = (const int*)  d_in[1];
    const float* ln1g  = (const float*)d_in[2];
    const float* ln1b  = (const float*)d_in[3];
    const float* bqkv  = (const float*)d_in[5];
    const float* bproj = (const float*)d_in[7];
    const float* ln2g  = (const float*)d_in[8];
    const float* ln2b  = (const float*)d_in[9];
    const float* bfc1  = (const float*)d_in[11];
    const float* bfc2  = (const float*)d_in[13];
    float* out = (float*)d_out;

    cudaFuncSetAttribute(gemm192_kernel<6, 0>, cudaFuncAttributeMaxDynamicSharedMemorySize, G192_SM);
    cudaFuncSetAttribute(gemm192_kernel<2, 1>, cudaFuncAttributeMaxDynamicSharedMemorySize, G192_SM);
    cudaFuncSetAttribute(gemm192_kernel<8, 2>, cudaFuncAttributeMaxDynamicSharedMemorySize, G192_SM);
    cudaFuncSetAttribute(fc2_kernel, cudaFuncAttributeMaxDynamicSharedMemorySize, FC2_SM);
    cudaFuncSetAttribute(attn_core,  cudaFuncAttributeMaxDynamicSharedMemorySize, AT_SM);

    cvt_all<<<576, 256>>>((const float*)d_in[4], (const float*)d_in[6],
                          (const float*)d_in[10], (const float*)d_in[12]);
    gemm192_kernel<6, 0><<<1568, 256, G192_SM>>>(x, ln1g, ln1b, bqkv);
    attn_core<<<4096, 256, AT_SM>>>(msk);
    gemm192_kernel<2, 1><<<1568, 256, G192_SM>>>(x, (const float*)0, (const float*)0, bproj);
    gemm192_kernel<8, 2><<<1568, 256, G192_SM>>>((const float*)0, ln2g, ln2b, bfc1);
    fc2_kernel<<<3136, 256, FC2_SM>>>(bfc2, out);
}

// round 14
// speedup vs baseline: 1.1843x; 1.1326x over previous
#include <cuda_runtime.h>
#include <cuda_bf16.h>
#include <mma.h>
#include <math.h>
#include <cstdint>

using namespace nvcuda;
typedef __nv_bfloat16 bf16;

#define LN_EPS 1e-5f

// persistent scratch (device globals: allocation-free)
__device__ float g_xres[(size_t)200704 * 192];        // mid residual
__device__ bf16  g_qkv [(size_t)200704 * 576];        // LN1 @ Wqkv^T + b
__device__ bf16  g_attno[(size_t)200704 * 192];       // attention output (pre-proj)
__device__ bf16  g_hmid[(size_t)200704 * 768];        // GELU(fc1)
__device__ bf16  g_wqkv[576 * 192];
__device__ bf16  g_wproj[192 * 192];
__device__ bf16  g_wfc1[768 * 192];
__device__ bf16  g_wfc2[192 * 768];

typedef wmma::fragment<wmma::matrix_a, 16, 16, 16, bf16, wmma::row_major> FA;
typedef wmma::fragment<wmma::matrix_b, 16, 16, 16, bf16, wmma::col_major> FBc;
typedef wmma::fragment<wmma::matrix_b, 16, 16, 16, bf16, wmma::row_major> FBr;
typedef wmma::fragment<wmma::accumulator, 16, 16, 16, float> FC;

// ---------------------------------------------------------------------------
__device__ __forceinline__ void cpa16(void* smem_dst, const void* gsrc) {
    unsigned int a = (unsigned int)__cvta_generic_to_shared(smem_dst);
    asm volatile("cp.async.cg.shared.global [%0], [%1], 16;\n" :: "r"(a), "l"(gsrc));
}
#define CP_COMMIT() asm volatile("cp.async.commit_group;\n" ::: "memory")
#define CP_WAIT0()  asm volatile("cp.async.wait_group 0;\n" ::: "memory")

// ---------------------------------------------------------------------------
__global__ void cvt_all(const float* __restrict__ wqkv, const float* __restrict__ wproj,
                        const float* __restrict__ wfc1, const float* __restrict__ wfc2)
{
    int i = blockIdx.x * 256 + threadIdx.x;
    if (i < 110592) g_wqkv[i]  = __float2bfloat16(wqkv[i]);
    if (i < 36864)  g_wproj[i] = __float2bfloat16(wproj[i]);
    if (i < 147456) {
        g_wfc1[i] = __float2bfloat16(wfc1[i]);
        g_wfc2[i] = __float2bfloat16(wfc2[i]);
    }
}

// ---------------------------------------------------------------------------
// smem (K=192 kernels): As 128x200 bf16 (51200) | Bbuf0/1 96x104 bf16 (19968
// each) | epi region 13312 B (4-phase buf 64x52 f32, or 8x 320-f32 warp ws)
// = 104448 B -> 2 CTAs/SM
// ---------------------------------------------------------------------------
#define G192_SM (51200 + 2 * 19968 + 13312)
#define FC2_SM  (2 * 26624 + 2 * 19968 + 13312)

__device__ __forceinline__ void stage_A_ln(bf16* As, const float* __restrict__ xr,
                                           const float* __restrict__ g,
                                           const float* __restrict__ b,
                                           int wid, int lane)
{
    for (int r = wid; r < 128; r += 8) {
        float v[6]; float s = 0.f;
#pragma unroll
        for (int j = 0; j < 6; j++) { v[j] = xr[r * 192 + j * 32 + lane]; s += v[j]; }
#pragma unroll
        for (int o = 16; o; o >>= 1) s += __shfl_xor_sync(0xffffffffu, s, o);
        float mu = s * (1.f / 192.f);
        float va = 0.f;
#pragma unroll
        for (int j = 0; j < 6; j++) { float d = v[j] - mu; va += d * d; }
#pragma unroll
        for (int o = 16; o; o >>= 1) va += __shfl_xor_sync(0xffffffffu, va, o);
        float rstd = rsqrtf(va * (1.f / 192.f) + LN_EPS);
#pragma unroll
        for (int j = 0; j < 6; j++) {
            int c = j * 32 + lane;
            As[r * 200 + c] = __float2bfloat16((v[j] - mu) * rstd * g[c] + b[c]);
        }
    }
}

// async-copy one 96x96 B tile (rows of W[N,K] at n0.., cols k0..): 1152 x 16B
__device__ __forceinline__ void copy_B_tile(bf16* Bs, const bf16* __restrict__ W,
                                            int ldw, int n0, int k0, int tid)
{
    const bf16* src = W + (size_t)n0 * ldw + k0;
    for (int idx = tid; idx < 96 * 12; idx += 256) {
        int r = idx / 12, ch = (idx - r * 12) * 8;
        cpa16(Bs + r * 104 + ch, src + (size_t)r * ldw + ch);
    }
}

// async-copy 128x96 A chunk (ld 104)
__device__ __forceinline__ void copy_A_chunk(bf16* Ad, const bf16* __restrict__ src,
                                             int lds, int tid)
{
    for (int idx = tid; idx < 128 * 12; idx += 256) {
        int r = idx / 12, ch = (idx - r * 12) * 8;
        cpa16(Ad + r * 104 + ch, src + (size_t)r * lds + ch);
    }
}

// mma over one 96-K chunk: A from As (ld ldA, k offset kbase), B from Bs (ld 104)
__device__ __forceinline__ void mma_chunk(const bf16* As, int ldA, int kbase,
                                          const bf16* Bs, int mt, int ng, FC acc[6])
{
#pragma unroll
    for (int kk = 0; kk < 96; kk += 16) {
        FA a0, a1;
        wmma::load_matrix_sync(a0, As + (mt * 32) * ldA + kbase + kk, ldA);
        wmma::load_matrix_sync(a1, As + (mt * 32 + 16) * ldA + kbase + kk, ldA);
#pragma unroll
        for (int j = 0; j < 3; j++) {
            FBc b;
            wmma::load_matrix_sync(b, Bs + (ng * 48 + j * 16) * 104 + kk, 104);
            wmma::mma_sync(acc[j],     a0, b, acc[j]);
            wmma::mma_sync(acc[j + 3], a1, b, acc[j + 3]);
        }
    }
}

// ---------------------------------------------------------------------------
// Per-warp barrier-free epilogue (best for many-slice kernels: qkv, fc1).
// OP: 0=qkv(+b->bf16) 2=fc1(+b,gelu->bf16)
// ---------------------------------------------------------------------------
template <int OP>
__device__ __forceinline__ void epi_frags(float* ws, FC acc[6], int mt, int ng,
                                          int cbase, int row0,
                                          const float* __restrict__ bias, int lane)
{
#pragma unroll
    for (int j = 0; j < 6; j++) {
        int r0 = row0 + mt * 32 + (j >= 3 ? 16 : 0);
        int c0 = cbase + ng * 48 + (j % 3) * 16;
        wmma::store_matrix_sync(ws, acc[j], 20, wmma::mem_row_major);
        __syncwarp();
        int rr = lane >> 1, cc = (lane & 1) * 8;
        const float* sp = ws + rr * 20 + cc;
        int gr = r0 + rr, gc = c0 + cc;
        if (OP == 0) {
            uint4 u; bf16* pb = (bf16*)&u;
#pragma unroll
            for (int q = 0; q < 8; q++) pb[q] = __float2bfloat16(sp[q] + bias[gc + q]);
            *(uint4*)(g_qkv + (size_t)gr * 576 + gc) = u;
        } else {
            uint4 u; bf16* pb = (bf16*)&u;
#pragma unroll
            for (int q = 0; q < 8; q++) {
                float v = sp[q] + bias[gc + q];
                v = 0.5f * v * (1.f + erff(v * 0.70710678118654752f));
                pb[q] = __float2bfloat16(v);
            }
            *(uint4*)(g_hmid + (size_t)gr * 768 + gc) = u;
        }
        __syncwarp();
    }
}

// ---------------------------------------------------------------------------
// Coalesced block-staged epilogue (best for few-slice kernels: proj, fc2).
// 4 phases; phase ph covers rows [h*64, +64) x cols [c*48, +48).
// OP: 1=proj(+b+x->f32 g_xres) 3=fc2(+b+xres->out f32)
// ---------------------------------------------------------------------------
template <int OP>
__device__ __forceinline__ void epi_slice(float* buf, FC acc[6], int mt, int ng,
                                          int cbase, int row0,
                                          const float* __restrict__ xin,
                                          const float* __restrict__ bias,
                                          float* __restrict__ outp, int tid)
{
#pragma unroll
    for (int ph = 0; ph < 4; ph++) {
        const int h = ph >> 1, c = ph & 1;
        __syncthreads();
        if ((mt >> 1) == h && ng == c) {
            int lr = (mt & 1) * 32;
#pragma unroll
            for (int j = 0; j < 3; j++) {
                wmma::store_matrix_sync(buf + lr * 52 + j * 16,        acc[j],     52, wmma::mem_row_major);
                wmma::store_matrix_sync(buf + (lr + 16) * 52 + j * 16, acc[j + 3], 52, wmma::mem_row_major);
            }
        }
        __syncthreads();
        for (int idx = tid; idx < 64 * 48; idx += 256) {
            int r = idx / 48, cc = idx - r * 48;
            int gr = row0 + h * 64 + r;
            int gc = cbase + c * 48 + cc;
            float v = buf[r * 52 + cc] + bias[gc];
            if (OP == 1) {
                size_t gi = (size_t)gr * 192 + gc;
                g_xres[gi] = v + xin[gi];
            } else {
                size_t gi = (size_t)gr * 192 + gc;
                outp[gi] = v + g_xres[gi];
            }
        }
    }
}

// ---------------------------------------------------------------------------
// Unified K=192 GEMM: CTA = 128 rows, N = NSLICES*96, cp.async-pipelined
// 96x96 B tiles. Epilogue: per-warp (OP0/OP2) or staged (OP1).
// ---------------------------------------------------------------------------
template <int NSLICES, int OP>
__global__ __launch_bounds__(256) void gemm192_kernel(
    const float* __restrict__ xin, const float* __restrict__ lng,
    const float* __restrict__ lnb, const float* __restrict__ bias)
{
    extern __shared__ char smc[];
    bf16*  As   = (bf16*)smc;
    bf16*  Bb0  = (bf16*)(smc + 51200);
    bf16*  Bb1  = (bf16*)(smc + 51200 + 19968);
    float* epi  = (float*)(smc + 51200 + 2 * 19968);

    const bf16* W = (OP == 0) ? g_wqkv : ((OP == 1) ? g_wproj : g_wfc1);

    const int tid = threadIdx.x, wid = tid >> 5, lane = tid & 31;
    const int row0 = blockIdx.x * 128;
    const int mt = wid & 3, ng = wid >> 2;
    float* ws = epi + wid * 320;

    copy_B_tile(Bb0, W, 192, 0, 0, tid);
    if (OP == 1) {
        const bf16* src = g_attno + (size_t)row0 * 192;
        for (int idx = tid; idx < 128 * 24; idx += 256) {
            int r = idx / 24, ch = (idx - r * 24) * 8;
            cpa16(As + r * 200 + ch, src + (size_t)r * 192 + ch);
        }
    }
    CP_COMMIT();

    if (OP == 0) stage_A_ln(As, xin + (size_t)row0 * 192, lng, lnb, wid, lane);
    if (OP == 2) stage_A_ln(As, g_xres + (size_t)row0 * 192, lng, lnb, wid, lane);

    FC acc[6];
#pragma unroll
    for (int j = 0; j < 6; j++) wmma::fill_fragment(acc[j], 0.f);

    const int T = NSLICES * 2;
    for (int t = 0; t < T; t++) {
        const int s = t >> 1, c = t & 1;
        bf16* Bcur = (t & 1) ? Bb1 : Bb0;
        bf16* Bnxt = (t & 1) ? Bb0 : Bb1;
        CP_WAIT0();
        __syncthreads();
        if (t + 1 < T) {
            copy_B_tile(Bnxt, W, 192, ((t + 1) >> 1) * 96, ((t + 1) & 1) * 96, tid);
            CP_COMMIT();
        }
        mma_chunk(As, 200, c * 96, Bcur, mt, ng, acc);
        if (c == 1) {
            if (OP == 1)
                epi_slice<1>(epi, acc, mt, ng, s * 96, row0, xin, bias, (float*)0, tid);
            else
                epi_frags<OP>(ws, acc, mt, ng, s * 96, row0, bias, lane);
#pragma unroll
            for (int j = 0; j < 6; j++) wmma::fill_fragment(acc[j], 0.f);
        }
    }
}

// ---------------------------------------------------------------------------
// FC2: grid 3136, paired: n0=(bid&1)*96, row0=(bid>>1)*128 so both 96-col
// slices of the same 128 rows share g_hmid reads in L2.
// K = 768 in 8 cp.async-pipelined chunks, persistent acc; + residual -> out
// ---------------------------------------------------------------------------
__global__ __launch_bounds__(256) void fc2_kernel(
    const float* __restrict__ bfc2, float* __restrict__ out)
{
    extern __shared__ char smc[];
    bf16*  Ab0  = (bf16*)smc;
    bf16*  Ab1  = (bf16*)(smc + 26624);
    bf16*  Bb0  = (bf16*)(smc + 2 * 26624);
    bf16*  Bb1  = (bf16*)(smc + 2 * 26624 + 19968);
    float* buf  = (float*)(smc + 2 * 26624 + 2 * 19968);

    const int tid = threadIdx.x, wid = tid >> 5;
    const int bid = blockIdx.x;
    const int row0 = (bid >> 1) * 128;
    const int n0 = (bid & 1) * 96;
    const int mt = wid & 3, ng = wid >> 2;

    copy_A_chunk(Ab0, g_hmid + (size_t)row0 * 768, 768, tid);
    copy_B_tile(Bb0, g_wfc2, 768, n0, 0, tid);
    CP_COMMIT();

    FC acc[6];
#pragma unroll
    for (int j = 0; j < 6; j++) wmma::fill_fragment(acc[j], 0.f);

    for (int t = 0; t < 8; t++) {
        bf16* Acur = (t & 1) ? Ab1 : Ab0;
        bf16* Bcur = (t & 1) ? Bb1 : Bb0;
        bf16* Anxt = (t & 1) ? Ab0 : Ab1;
        bf16* Bnxt = (t & 1) ? Bb0 : Bb1;
        CP_WAIT0();
        __syncthreads();
        if (t + 1 < 8) {
            copy_A_chunk(Anxt, g_hmid + (size_t)row0 * 768 + (t + 1) * 96, 768, tid);
            copy_B_tile(Bnxt, g_wfc2, 768, n0, (t + 1) * 96, tid);
            CP_COMMIT();
        }
        mma_chunk(Acur, 104, 0, Bcur, mt, ng, acc);
    }
    epi_slice<3>(buf, acc, mt, ng, n0, row0, (const float*)0, bfc2, out, tid);
}

// ---------------------------------------------------------------------------
// attention core v2: ONE CTA PER WINDOW, loop over 6 heads with cp.async
// double-buffered q/k/v head slices; mask converted once to 64-bit bitmasks.
// smem = 57856 B -> 3 CTAs/SM
// ---------------------------------------------------------------------------
#define AT_SM (2 * 15360 + 17408 + 9216 + 512)

__device__ __forceinline__ void stage_qkv_head(bf16* dst, size_t base, int h, int tid)
{
    for (int idx = tid; idx < 588; idx += 256) {
        int m = idx / 196, rem = idx - m * 196;
        int r = rem >> 2, c8 = (rem & 3) * 8;
        cpa16(dst + m * 2560 + r * 40 + c8,
              g_qkv + base + (size_t)r * 576 + m * 192 + h * 32 + c8);
    }
}

__global__ __launch_bounds__(256) void attn_core(const int* __restrict__ mask)
{
    extern __shared__ char smc[];
    bf16*  qkvb0 = (bf16*)smc;                    // q@0 k@2560 v@5120 (elems)
    bf16*  qkvb1 = (bf16*)(smc + 15360);
    float* S     = (float*)(smc + 30720);         // 64x68 f32
    bf16*  P     = (bf16*)(smc + 48128);          // 64x72
    unsigned long long* mb = (unsigned long long*)(smc + 57344);
    float* pvbuf = S;                             // alias

    const int tid = threadIdx.x, wid = tid >> 5, lane = tid & 31;
    const int win = blockIdx.x;
    const size_t base = (size_t)(win * 49) * 576;

    {
        const int* mrow_base = mask + (size_t)win * 49 * 49;
        for (int r = wid; r < 49; r += 8) {
            const int* mrow = mrow_base + r * 49;
            unsigned m1 = __ballot_sync(0xffffffffu, mrow[lane] != 0);
            unsigned m2 = __ballot_sync(0xffffffffu,
                                        (lane + 32 < 49) ? (mrow[lane + 32] != 0) : 0);
            if (lane == 0) mb[r] = ((unsigned long long)m2 << 32) | m1;
        }
    }
    for (int idx = tid; idx < 150; idx += 256) {
        int b = idx / 75, e = idx - b * 75;
        int r = 49 + e / 5, c8 = (e % 5) * 8;
        bf16* vdst = (b ? qkvb1 : qkvb0) + 5120 + r * 40 + c8;
        uint4 z; z.x = z.y = z.z = z.w = 0u;
        *(uint4*)vdst = z;
    }

    stage_qkv_head(qkvb0, base, 0, tid);
    CP_COMMIT();
    __syncthreads();

    for (int h = 0; h < 6; h++) {
        bf16* cur = (h & 1) ? qkvb1 : qkvb0;
        bf16* nxt = (h & 1) ? qkvb0 : qkvb1;
        CP_WAIT0();
        __syncthreads();
        if (h + 1 < 6) {
            stage_qkv_head(nxt, base, h + 1, tid);
            CP_COMMIT();
        }
        bf16* qs = cur, *ks = cur + 2560, *vs = cur + 5120;

#pragma unroll
        for (int it = 0; it < 2; it++) {
            int t = wid + it * 8;
            int mt = t & 3, nt = t >> 2;
            FC c;
            wmma::fill_fragment(c, 0.f);
#pragma unroll
            for (int k0 = 0; k0 < 32; k0 += 16) {
                FA a;
                wmma::load_matrix_sync(a, qs + mt * 16 * 40 + k0, 40);
                FBc b;
                wmma::load_matrix_sync(b, ks + nt * 16 * 40 + k0, 40);
                wmma::mma_sync(c, a, b, c);
            }
            wmma::store_matrix_sync(S + mt * 16 * 68 + nt * 16, c, 68, wmma::mem_row_major);
        }
        __syncthreads();

        {
            const float scale = 0.17677669529663687f;
            for (int r = wid; r < 49; r += 8) {
                unsigned long long bits = mb[r];
                int j2 = lane + 32;
                bool m1 = (bits >> lane) & 1ull;
                bool m2 = (j2 < 49) && ((bits >> j2) & 1ull);
                float s1 = m1 ? S[r * 68 + lane] * scale : -1e30f;
                float s2 = m2 ? S[r * 68 + j2] * scale : -1e30f;
                float m = fmaxf(s1, s2);
#pragma unroll
                for (int o = 16; o; o >>= 1) m = fmaxf(m, __shfl_xor_sync(0xffffffffu, m, o));
                float e1 = __expf(s1 - m);
                float e2 = (j2 < 49) ? __expf(s2 - m) : 0.f;
                float sum = e1 + e2;
#pragma unroll
                for (int o = 16; o; o >>= 1) sum += __shfl_xor_sync(0xffffffffu, sum, o);
                float inv = 1.f / sum;
                P[r * 72 + lane] = __float2bfloat16(e1 * inv);
                P[r * 72 + j2]   = __float2bfloat16(e2 * inv);
            }
        }
        __syncthreads();

        {
            int mt = wid & 3, nt = wid >> 2;
            FC c;
            wmma::fill_fragment(c, 0.f);
#pragma unroll
            for (int k0 = 0; k0 < 64; k0 += 16) {
                FA a;
                wmma::load_matrix_sync(a, P + mt * 16 * 72 + k0, 72);
                FBr b;
                wmma::load_matrix_sync(b, vs + k0 * 40 + nt * 16, 40);
                wmma::mma_sync(c, a, b, c);
            }
            wmma::store_matrix_sync(pvbuf + mt * 16 * 40 + nt * 16, c, 40, wmma::mem_row_major);
        }
        __syncthreads();

        for (int idx = tid; idx < 49 * 32; idx += 256) {
            int r = idx >> 5, c = idx & 31;
            g_attno[(size_t)(win * 49 + r) * 192 + h * 32 + c] =
                __float2bfloat16(pvbuf[r * 40 + c]);
        }
        __syncthreads();
    }
}

// ---------------------------------------------------------------------------

extern "C" void kernel_launch(void* const* d_in, const int* in_sizes, int n_in,
                              void* d_out, int out_size)
{
    const float* x     = (const float*)d_in[0];
    const int*   msk   = (const int*)  d_in[1];
    const float* ln1g  = (const float*)d_in[2];
    const float* ln1b  = (const float*)d_in[3];
    const float* bqkv  = (const float*)d_in[5];
    const float* bproj = (const float*)d_in[7];
    const float* ln2g  = (const float*)d_in[8];
    const float* ln2b  = (const float*)d_in[9];
    const float* bfc1  = (const float*)d_in[11];
    const float* bfc2  = (const float*)d_in[13];
    float* out = (float*)d_out;

    cudaFuncSetAttribute(gemm192_kernel<6, 0>, cudaFuncAttributeMaxDynamicSharedMemorySize, G192_SM);
    cudaFuncSetAttribute(gemm192_kernel<2, 1>, cudaFuncAttributeMaxDynamicSharedMemorySize, G192_SM);
    cudaFuncSetAttribute(gemm192_kernel<8, 2>, cudaFuncAttributeMaxDynamicSharedMemorySize, G192_SM);
    cudaFuncSetAttribute(fc2_kernel, cudaFuncAttributeMaxDynamicSharedMemorySize, FC2_SM);
    cudaFuncSetAttribute(attn_core,  cudaFuncAttributeMaxDynamicSharedMemorySize, AT_SM);

    cvt_all<<<576, 256>>>((const float*)d_in[4], (const float*)d_in[6],
                          (const float*)d_in[10], (const float*)d_in[12]);
    gemm192_kernel<6, 0><<<1568, 256, G192_SM>>>(x, ln1g, ln1b, bqkv);
    attn_core<<<4096, 256, AT_SM>>>(msk);
    gemm192_kernel<2, 1><<<1568, 256, G192_SM>>>(x, (const float*)0, (const float*)0, bproj);
    gemm192_kernel<8, 2><<<1568, 256, G192_SM>>>((const float*)0, ln2g, ln2b, bfc1);
    fc2_kernel<<<3136, 256, FC2_SM>>>(bfc2, out);
}

// round 15
// speedup vs baseline: 1.1855x; 1.0011x over previous
#include <cuda_runtime.h>
#include <cuda_bf16.h>
#include <mma.h>
#include <math.h>
#include <cstdint>

using namespace nvcuda;
typedef __nv_bfloat16 bf16;

#define LN_EPS 1e-5f

// persistent scratch (device globals: allocation-free)
__device__ float g_xres[(size_t)200704 * 192];        // mid residual
__device__ bf16  g_qkv [(size_t)200704 * 576];        // LN1 @ Wqkv^T + b
__device__ bf16  g_attno[(size_t)200704 * 192];       // attention output (pre-proj)
__device__ bf16  g_wqkv[576 * 192];
__device__ bf16  g_wproj[192 * 192];
__device__ bf16  g_wfc1[768 * 192];
__device__ bf16  g_wfc2[192 * 768];

typedef wmma::fragment<wmma::matrix_a, 16, 16, 16, bf16, wmma::row_major> FA;
typedef wmma::fragment<wmma::matrix_b, 16, 16, 16, bf16, wmma::col_major> FBc;
typedef wmma::fragment<wmma::matrix_b, 16, 16, 16, bf16, wmma::row_major> FBr;
typedef wmma::fragment<wmma::accumulator, 16, 16, 16, float> FC;

// ---------------------------------------------------------------------------
__device__ __forceinline__ void cpa16(void* smem_dst, const void* gsrc) {
    unsigned int a = (unsigned int)__cvta_generic_to_shared(smem_dst);
    asm volatile("cp.async.cg.shared.global [%0], [%1], 16;\n" :: "r"(a), "l"(gsrc));
}
#define CP_COMMIT() asm volatile("cp.async.commit_group;\n" ::: "memory")
#define CP_WAIT0()  asm volatile("cp.async.wait_group 0;\n" ::: "memory")

// ---------------------------------------------------------------------------
__global__ void cvt_all(const float* __restrict__ wqkv, const float* __restrict__ wproj,
                        const float* __restrict__ wfc1, const float* __restrict__ wfc2)
{
    int i = blockIdx.x * 256 + threadIdx.x;
    if (i < 110592) g_wqkv[i]  = __float2bfloat16(wqkv[i]);
    if (i < 36864)  g_wproj[i] = __float2bfloat16(wproj[i]);
    if (i < 147456) {
        g_wfc1[i] = __float2bfloat16(wfc1[i]);
        g_wfc2[i] = __float2bfloat16(wfc2[i]);
    }
}

// ---------------------------------------------------------------------------
// shared helpers
// ---------------------------------------------------------------------------
#define G192_SM (51200 + 2 * 19968 + 13312)

template <int NTHREADS>
__device__ __forceinline__ void stage_A_ln_t(bf16* As, const float* __restrict__ xr,
                                             const float* __restrict__ g,
                                             const float* __restrict__ b,
                                             int wid, int lane)
{
    for (int r = wid; r < 128; r += NTHREADS / 32) {
        float v[6]; float s = 0.f;
#pragma unroll
        for (int j = 0; j < 6; j++) { v[j] = xr[r * 192 + j * 32 + lane]; s += v[j]; }
#pragma unroll
        for (int o = 16; o; o >>= 1) s += __shfl_xor_sync(0xffffffffu, s, o);
        float mu = s * (1.f / 192.f);
        float va = 0.f;
#pragma unroll
        for (int j = 0; j < 6; j++) { float d = v[j] - mu; va += d * d; }
#pragma unroll
        for (int o = 16; o; o >>= 1) va += __shfl_xor_sync(0xffffffffu, va, o);
        float rstd = rsqrtf(va * (1.f / 192.f) + LN_EPS);
#pragma unroll
        for (int j = 0; j < 6; j++) {
            int c = j * 32 + lane;
            As[r * 200 + c] = __float2bfloat16((v[j] - mu) * rstd * g[c] + b[c]);
        }
    }
}

// async-copy one 96x96 B tile (256-thread)
__device__ __forceinline__ void copy_B_tile(bf16* Bs, const bf16* __restrict__ W,
                                            int ldw, int n0, int k0, int tid)
{
    const bf16* src = W + (size_t)n0 * ldw + k0;
    for (int idx = tid; idx < 96 * 12; idx += 256) {
        int r = idx / 12, ch = (idx - r * 12) * 8;
        cpa16(Bs + r * 104 + ch, src + (size_t)r * ldw + ch);
    }
}

// generic async tile copy: ROWS x (CH16*8 cols), ld dst, NTHREADS threads
template <int ROWS, int CH16, int NTHREADS, int LDD>
__device__ __forceinline__ void copy_tile(bf16* dst, const bf16* __restrict__ src,
                                          int lds, int tid)
{
    for (int idx = tid; idx < ROWS * CH16; idx += NTHREADS) {
        int r = idx / CH16, ch = (idx - r * CH16) * 8;
        cpa16(dst + r * LDD + ch, src + (size_t)r * lds + ch);
    }
}

// mma over one 96-K chunk (warp tile 32x48)
__device__ __forceinline__ void mma_chunk(const bf16* As, int ldA, int kbase,
                                          const bf16* Bs, int mt, int ng, FC acc[6])
{
#pragma unroll
    for (int kk = 0; kk < 96; kk += 16) {
        FA a0, a1;
        wmma::load_matrix_sync(a0, As + (mt * 32) * ldA + kbase + kk, ldA);
        wmma::load_matrix_sync(a1, As + (mt * 32 + 16) * ldA + kbase + kk, ldA);
#pragma unroll
        for (int j = 0; j < 3; j++) {
            FBc b;
            wmma::load_matrix_sync(b, Bs + (ng * 48 + j * 16) * 104 + kk, 104);
            wmma::mma_sync(acc[j],     a0, b, acc[j]);
            wmma::mma_sync(acc[j + 3], a1, b, acc[j + 3]);
        }
    }
}

// ---------------------------------------------------------------------------
// Per-warp barrier-free epilogue (qkv)
// ---------------------------------------------------------------------------
__device__ __forceinline__ void epi_frags_qkv(float* ws, FC acc[6], int mt, int ng,
                                              int cbase, int row0,
                                              const float* __restrict__ bias, int lane)
{
#pragma unroll
    for (int j = 0; j < 6; j++) {
        int r0 = row0 + mt * 32 + (j >= 3 ? 16 : 0);
        int c0 = cbase + ng * 48 + (j % 3) * 16;
        wmma::store_matrix_sync(ws, acc[j], 20, wmma::mem_row_major);
        __syncwarp();
        int rr = lane >> 1, cc = (lane & 1) * 8;
        const float* sp = ws + rr * 20 + cc;
        int gr = r0 + rr, gc = c0 + cc;
        uint4 u; bf16* pb = (bf16*)&u;
#pragma unroll
        for (int q = 0; q < 8; q++) pb[q] = __float2bfloat16(sp[q] + bias[gc + q]);
        *(uint4*)(g_qkv + (size_t)gr * 576 + gc) = u;
        __syncwarp();
    }
}

// ---------------------------------------------------------------------------
// Coalesced block-staged epilogue for proj (OP1): +b + x -> g_xres
// ---------------------------------------------------------------------------
__device__ __forceinline__ void epi_slice_proj(float* buf, FC acc[6], int mt, int ng,
                                               int cbase, int row0,
                                               const float* __restrict__ xin,
                                               const float* __restrict__ bias, int tid)
{
#pragma unroll
    for (int ph = 0; ph < 4; ph++) {
        const int h = ph >> 1, c = ph & 1;
        __syncthreads();
        if ((mt >> 1) == h && ng == c) {
            int lr = (mt & 1) * 32;
#pragma unroll
            for (int j = 0; j < 3; j++) {
                wmma::store_matrix_sync(buf + lr * 52 + j * 16,        acc[j],     52, wmma::mem_row_major);
                wmma::store_matrix_sync(buf + (lr + 16) * 52 + j * 16, acc[j + 3], 52, wmma::mem_row_major);
            }
        }
        __syncthreads();
        for (int idx = tid; idx < 64 * 48; idx += 256) {
            int r = idx / 48, cc = idx - r * 48;
            int gr = row0 + h * 64 + r;
            int gc = cbase + c * 48 + cc;
            size_t gi = (size_t)gr * 192 + gc;
            g_xres[gi] = buf[r * 52 + cc] + bias[gc] + xin[gi];
        }
    }
}

// ---------------------------------------------------------------------------
// Unified K=192 GEMM (qkv OP0, proj OP1): block 256, CTA = 128 rows,
// cp.async-pipelined 96x96 B tiles.
// ---------------------------------------------------------------------------
template <int NSLICES, int OP>
__global__ __launch_bounds__(256) void gemm192_kernel(
    const float* __restrict__ xin, const float* __restrict__ lng,
    const float* __restrict__ lnb, const float* __restrict__ bias)
{
    extern __shared__ char smc[];
    bf16*  As   = (bf16*)smc;
    bf16*  Bb0  = (bf16*)(smc + 51200);
    bf16*  Bb1  = (bf16*)(smc + 51200 + 19968);
    float* epi  = (float*)(smc + 51200 + 2 * 19968);

    const bf16* W = (OP == 0) ? g_wqkv : g_wproj;

    const int tid = threadIdx.x, wid = tid >> 5, lane = tid & 31;
    const int row0 = blockIdx.x * 128;
    const int mt = wid & 3, ng = wid >> 2;
    float* ws = epi + wid * 320;

    copy_B_tile(Bb0, W, 192, 0, 0, tid);
    if (OP == 1) {
        const bf16* src = g_attno + (size_t)row0 * 192;
        for (int idx = tid; idx < 128 * 24; idx += 256) {
            int r = idx / 24, ch = (idx - r * 24) * 8;
            cpa16(As + r * 200 + ch, src + (size_t)r * 192 + ch);
        }
    }
    CP_COMMIT();

    if (OP == 0) stage_A_ln_t<256>(As, xin + (size_t)row0 * 192, lng, lnb, wid, lane);

    FC acc[6];
#pragma unroll
    for (int j = 0; j < 6; j++) wmma::fill_fragment(acc[j], 0.f);

    const int T = NSLICES * 2;
    for (int t = 0; t < T; t++) {
        const int s = t >> 1, c = t & 1;
        bf16* Bcur = (t & 1) ? Bb1 : Bb0;
        bf16* Bnxt = (t & 1) ? Bb0 : Bb1;
        CP_WAIT0();
        __syncthreads();
        if (t + 1 < T) {
            copy_B_tile(Bnxt, W, 192, ((t + 1) >> 1) * 96, ((t + 1) & 1) * 96, tid);
            CP_COMMIT();
        }
        mma_chunk(As, 200, c * 96, Bcur, mt, ng, acc);
        if (c == 1) {
            if (OP == 1)
                epi_slice_proj(epi, acc, mt, ng, s * 96, row0, xin, bias, tid);
            else
                epi_frags_qkv(ws, acc, mt, ng, s * 96, row0, bias, lane);
#pragma unroll
            for (int j = 0; j < 6; j++) wmma::fill_fragment(acc[j], 0.f);
        }
    }
}

// ---------------------------------------------------------------------------
// FUSED MLP: block 512 (16 warps), CTA = 128 rows, 1 CTA/SM.
// LN2 -> loop 8 hid-chunks of 96: fc1 (warp 16x48) -> bias+GELU -> hb (smem
// bf16) -> fc2 partial (warp 32x48, persistent acc) -> epilogue +bfc2 +xres.
// smem: xn 51200 | W1b 38400 | W2b 39936 | hb 26624 | ws/buf 20480 = 176640
// ---------------------------------------------------------------------------
#define MLP_SM (51200 + 38400 + 39936 + 26624 + 20480)

__global__ __launch_bounds__(512) void mlp_kernel(
    const float* __restrict__ ln2g, const float* __restrict__ ln2b,
    const float* __restrict__ bfc1, const float* __restrict__ bfc2,
    float* __restrict__ out)
{
    extern __shared__ char smc[];
    bf16*  xn  = (bf16*)smc;                       // 128x200
    bf16*  W1b = (bf16*)(smc + 51200);             // 96x200 (hid rows x K)
    bf16*  W2b = (bf16*)(smc + 51200 + 38400);     // 192x104 (out rows x k96)
    bf16*  hb  = (bf16*)(smc + 51200 + 38400 + 39936);  // 128x104
    float* wsb = (float*)(smc + 51200 + 38400 + 39936 + 26624); // 16x320 f32 / epi buf

    const int tid = threadIdx.x, wid = tid >> 5, lane = tid & 31;
    const int row0 = blockIdx.x * 128;
    // fc1 tiling: 16x48 per warp
    const int r16 = wid & 7, c2 = wid >> 3;
    // fc2 tiling: 32x48 per warp
    const int mtf = wid & 3, ngf = wid >> 2;
    float* ws = wsb + wid * 320;

    // prefetch W1[0] (96x192 -> ld 200) + W2[0] (192x96 -> ld 104)
    copy_tile<96, 24, 512, 200>(W1b, g_wfc1, 192, tid);
    copy_tile<192, 12, 512, 104>(W2b, g_wfc2, 768, tid);
    CP_COMMIT();

    stage_A_ln_t<512>(xn, g_xres + (size_t)row0 * 192, ln2g, ln2b, wid, lane);

    FC acc[6];
#pragma unroll
    for (int j = 0; j < 6; j++) wmma::fill_fragment(acc[j], 0.f);

    for (int p = 0; p < 8; p++) {
        CP_WAIT0();
        __syncthreads();                 // W1[p], W2[p] ready; hb free

        // fc1: h[128, 96] = xn @ W1b^T (warp tile 16x48)
        FC f[3];
#pragma unroll
        for (int j = 0; j < 3; j++) wmma::fill_fragment(f[j], 0.f);
#pragma unroll
        for (int k0 = 0; k0 < 192; k0 += 16) {
            FA a;
            wmma::load_matrix_sync(a, xn + (r16 * 16) * 200 + k0, 200);
#pragma unroll
            for (int j = 0; j < 3; j++) {
                FBc b;
                wmma::load_matrix_sync(b, W1b + (c2 * 48 + j * 16) * 200 + k0, 200);
                wmma::mma_sync(f[j], a, b, f[j]);
            }
        }
        // bias + GELU -> hb (per-warp, barrier-free)
#pragma unroll
        for (int j = 0; j < 3; j++) {
            wmma::store_matrix_sync(ws, f[j], 20, wmma::mem_row_major);
            __syncwarp();
            int rr = lane >> 1, cc = (lane & 1) * 8;
            const float* sp = ws + rr * 20 + cc;
            int lr = r16 * 16 + rr;
            int lc = c2 * 48 + j * 16 + cc;
            uint4 u; bf16* pb = (bf16*)&u;
#pragma unroll
            for (int q = 0; q < 8; q++) {
                float v = sp[q] + bfc1[p * 96 + lc + q];
                v = 0.5f * v * (1.f + erff(v * 0.70710678118654752f));
                pb[q] = __float2bfloat16(v);
            }
            *(uint4*)(hb + lr * 104 + lc) = u;
            __syncwarp();
        }
        __syncthreads();                 // hb complete; W1b free

        if (p + 1 < 8)                   // overlap W1 prefetch with fc2 mma
            copy_tile<96, 24, 512, 200>(W1b, g_wfc1 + (size_t)(p + 1) * 96 * 192, 192, tid);

        // fc2 partial: acc += hb @ W2b^T (warp tile 32x48, K=96)
        mma_chunk(hb, 104, 0, W2b, mtf, ngf, acc);
        __syncthreads();                 // all done reading W2b

        if (p + 1 < 8) {
            copy_tile<192, 12, 512, 104>(W2b, g_wfc2 + (size_t)(p + 1) * 96, 768, tid);
            CP_COMMIT();
        }
    }

    // epilogue: 8 phases (2 row-halves x 4 col-groups of 48), staged coalesced
    float* buf = wsb;                    // 64x52 f32 = 13312 <= 20480
#pragma unroll
    for (int h = 0; h < 2; h++)
#pragma unroll
        for (int c = 0; c < 4; c++) {
            __syncthreads();
            if ((mtf >> 1) == h && ngf == c) {
                int lr = (mtf & 1) * 32;
#pragma unroll
                for (int j = 0; j < 3; j++) {
                    wmma::store_matrix_sync(buf + lr * 52 + j * 16,        acc[j],     52, wmma::mem_row_major);
                    wmma::store_matrix_sync(buf + (lr + 16) * 52 + j * 16, acc[j + 3], 52, wmma::mem_row_major);
                }
            }
            __syncthreads();
            for (int idx = tid; idx < 64 * 48; idx += 512) {
                int r = idx / 48, cc = idx - r * 48;
                int gr = row0 + h * 64 + r;
                int gc = c * 48 + cc;
                size_t gi = (size_t)gr * 192 + gc;
                out[gi] = buf[r * 52 + cc] + bfc2[gc] + g_xres[gi];
            }
        }
}

// ---------------------------------------------------------------------------
// attention core v2: ONE CTA PER WINDOW, 6 heads, cp.async double-buffered
// q/k/v head slices; mask as 64-bit bitmasks.  smem 57856 -> 3 CTAs/SM
// ---------------------------------------------------------------------------
#define AT_SM (2 * 15360 + 17408 + 9216 + 512)

__device__ __forceinline__ void stage_qkv_head(bf16* dst, size_t base, int h, int tid)
{
    for (int idx = tid; idx < 588; idx += 256) {
        int m = idx / 196, rem = idx - m * 196;
        int r = rem >> 2, c8 = (rem & 3) * 8;
        cpa16(dst + m * 2560 + r * 40 + c8,
              g_qkv + base + (size_t)r * 576 + m * 192 + h * 32 + c8);
    }
}

__global__ __launch_bounds__(256) void attn_core(const int* __restrict__ mask)
{
    extern __shared__ char smc[];
    bf16*  qkvb0 = (bf16*)smc;
    bf16*  qkvb1 = (bf16*)(smc + 15360);
    float* S     = (float*)(smc + 30720);
    bf16*  P     = (bf16*)(smc + 48128);
    unsigned long long* mb = (unsigned long long*)(smc + 57344);
    float* pvbuf = S;

    const int tid = threadIdx.x, wid = tid >> 5, lane = tid & 31;
    const int win = blockIdx.x;
    const size_t base = (size_t)(win * 49) * 576;

    {
        const int* mrow_base = mask + (size_t)win * 49 * 49;
        for (int r = wid; r < 49; r += 8) {
            const int* mrow = mrow_base + r * 49;
            unsigned m1 = __ballot_sync(0xffffffffu, mrow[lane] != 0);
            unsigned m2 = __ballot_sync(0xffffffffu,
                                        (lane + 32 < 49) ? (mrow[lane + 32] != 0) : 0);
            if (lane == 0) mb[r] = ((unsigned long long)m2 << 32) | m1;
        }
    }
    for (int idx = tid; idx < 150; idx += 256) {
        int b = idx / 75, e = idx - b * 75;
        int r = 49 + e / 5, c8 = (e % 5) * 8;
        bf16* vdst = (b ? qkvb1 : qkvb0) + 5120 + r * 40 + c8;
        uint4 z; z.x = z.y = z.z = z.w = 0u;
        *(uint4*)vdst = z;
    }

    stage_qkv_head(qkvb0, base, 0, tid);
    CP_COMMIT();
    __syncthreads();

    for (int h = 0; h < 6; h++) {
        bf16* cur = (h & 1) ? qkvb1 : qkvb0;
        bf16* nxt = (h & 1) ? qkvb0 : qkvb1;
        CP_WAIT0();
        __syncthreads();
        if (h + 1 < 6) {
            stage_qkv_head(nxt, base, h + 1, tid);
            CP_COMMIT();
        }
        bf16* qs = cur, *ks = cur + 2560, *vs = cur + 5120;

#pragma unroll
        for (int it = 0; it < 2; it++) {
            int t = wid + it * 8;
            int mt = t & 3, nt = t >> 2;
            FC c;
            wmma::fill_fragment(c, 0.f);
#pragma unroll
            for (int k0 = 0; k0 < 32; k0 += 16) {
                FA a;
                wmma::load_matrix_sync(a, qs + mt * 16 * 40 + k0, 40);
                FBc b;
                wmma::load_matrix_sync(b, ks + nt * 16 * 40 + k0, 40);
                wmma::mma_sync(c, a, b, c);
            }
            wmma::store_matrix_sync(S + mt * 16 * 68 + nt * 16, c, 68, wmma::mem_row_major);
        }
        __syncthreads();

        {
            const float scale = 0.17677669529663687f;
            for (int r = wid; r < 49; r += 8) {
                unsigned long long bits = mb[r];
                int j2 = lane + 32;
                bool m1 = (bits >> lane) & 1ull;
                bool m2 = (j2 < 49) && ((bits >> j2) & 1ull);
                float s1 = m1 ? S[r * 68 + lane] * scale : -1e30f;
                float s2 = m2 ? S[r * 68 + j2] * scale : -1e30f;
                float m = fmaxf(s1, s2);
#pragma unroll
                for (int o = 16; o; o >>= 1) m = fmaxf(m, __shfl_xor_sync(0xffffffffu, m, o));
                float e1 = __expf(s1 - m);
                float e2 = (j2 < 49) ? __expf(s2 - m) : 0.f;
                float sum = e1 + e2;
#pragma unroll
                for (int o = 16; o; o >>= 1) sum += __shfl_xor_sync(0xffffffffu, sum, o);
                float inv = 1.f / sum;
                P[r * 72 + lane] = __float2bfloat16(e1 * inv);
                P[r * 72 + j2]   = __float2bfloat16(e2 * inv);
            }
        }
        __syncthreads();

        {
            int mt = wid & 3, nt = wid >> 2;
            FC c;
            wmma::fill_fragment(c, 0.f);
#pragma unroll
            for (int k0 = 0; k0 < 64; k0 += 16) {
                FA a;
                wmma::load_matrix_sync(a, P + mt * 16 * 72 + k0, 72);
                FBr b;
                wmma::load_matrix_sync(b, vs + k0 * 40 + nt * 16, 40);
                wmma::mma_sync(c, a, b, c);
            }
            wmma::store_matrix_sync(pvbuf + mt * 16 * 40 + nt * 16, c, 40, wmma::mem_row_major);
        }
        __syncthreads();

        for (int idx = tid; idx < 49 * 32; idx += 256) {
            int r = idx >> 5, c = idx & 31;
            g_attno[(size_t)(win * 49 + r) * 192 + h * 32 + c] =
                __float2bfloat16(pvbuf[r * 40 + c]);
        }
        __syncthreads();
    }
}

// ---------------------------------------------------------------------------

extern "C" void kernel_launch(void* const* d_in, const int* in_sizes, int n_in,
                              void* d_out, int out_size)
{
    const float* x     = (const float*)d_in[0];
    const int*   msk   = (const int*)  d_in[1];
    const float* ln1g  = (const float*)d_in[2];
    const float* ln1b  = (const float*)d_in[3];
    const float* bqkv  = (const float*)d_in[5];
    const float* bproj = (const float*)d_in[7];
    const float* ln2g  = (const float*)d_in[8];
    const float* ln2b  = (const float*)d_in[9];
    const float* bfc1  = (const float*)d_in[11];
    const float* bfc2  = (const float*)d_in[13];
    float* out = (float*)d_out;

    cudaFuncSetAttribute(gemm192_kernel<6, 0>, cudaFuncAttributeMaxDynamicSharedMemorySize, G192_SM);
    cudaFuncSetAttribute(gemm192_kernel<2, 1>, cudaFuncAttributeMaxDynamicSharedMemorySize, G192_SM);
    cudaFuncSetAttribute(mlp_kernel, cudaFuncAttributeMaxDynamicSharedMemorySize, MLP_SM);
    cudaFuncSetAttribute(attn_core,  cudaFuncAttributeMaxDynamicSharedMemorySize, AT_SM);

    cvt_all<<<576, 256>>>((const float*)d_in[4], (const float*)d_in[6],
                          (const float*)d_in[10], (const float*)d_in[12]);
    gemm192_kernel<6, 0><<<1568, 256, G192_SM>>>(x, ln1g, ln1b, bqkv);
    attn_core<<<4096, 256, AT_SM>>>(msk);
    gemm192_kernel<2, 1><<<1568, 256, G192_SM>>>(x, (const float*)0, (const float*)0, bproj);
    mlp_kernel<<<1568, 512, MLP_SM>>>(ln2g, ln2b, bfc1, bfc2, out);
}